// round 2
// baseline (speedup 1.0000x reference)
#include <cuda_runtime.h>
#include <cuda_bf16.h>
#include <mma.h>

using namespace nvcuda;

#define T_   512
#define B_   128
#define D_   512
#define H_   1024
#define G3H  3072

// ---- gi_gemm tiling (unchanged from validated round-1) ----
#define MT   128
#define NT   64
#define KT   32
#define PADA 40
#define PADB 72

// ---- persistent scan tiling ----
#define NCTA    128      // CTAs; each owns 8 hidden cols x 3 gates
#define NCOLS   8        // hidden cols per CTA
#define NPACK   32       // packed cols in smem (24 real + 8 zero pad)
#define WH_LD   40       // bf16 leading dim for resident Wh slice
#define SKT     64       // K chunk for h staging
#define SA_LD   72       // bf16 leading dim for A stage
#define GH_LD   36       // f32 leading dim for gh epilogue tile

__device__ float        g_Gi[(long long)T_ * B_ * G3H];  // precomputed x@Wi+bi
__device__ int          g_reset_mode;
__device__ unsigned int g_bar;

// ---------------------------------------------------------------------------
__global__ void init_kernel(const unsigned char* __restrict__ resets) {
    const unsigned int* w = (const unsigned int*)resets;
    bool i32 = true, f32 = true;
    for (int i = 0; i < 16; i++) {
        unsigned int v = w[i];
        if (v != 0u && v != 1u) i32 = false;
        if (v != 0u && v != 0x3F800000u) f32 = false;
    }
    g_reset_mode = i32 ? 1 : (f32 ? 2 : 0);
    g_bar = 0u;
}

__device__ __forceinline__ bool get_reset(const void* r, int idx) {
    int m = g_reset_mode;
    if (m == 1) return ((const int*)r)[idx] != 0;
    if (m == 2) return ((const float*)r)[idx] != 0.0f;
    return ((const unsigned char*)r)[idx] != 0;
}

__device__ __forceinline__ void split2(float v, __nv_bfloat16& hi, __nv_bfloat16& lo) {
    hi = __float2bfloat16(v);
    lo = __float2bfloat16(v - __bfloat162float(hi));
}

// ---------------------------------------------------------------------------
// Phase B: Gi = X @ Wi + bi  (validated in round 1)
// ---------------------------------------------------------------------------
__global__ __launch_bounds__(256) void gi_gemm_kernel(
    const float* __restrict__ X,
    const float* __restrict__ Wi,
    const float* __restrict__ bi)
{
    __shared__ __align__(16) __nv_bfloat16 sAh[MT * PADA], sAl[MT * PADA];
    __shared__ __align__(16) __nv_bfloat16 sBh[KT * PADB], sBl[KT * PADB];
    __shared__ __align__(16) float sBias[16 * NT];

    const int n0  = blockIdx.x * NT;
    const long long m0 = (long long)blockIdx.y * MT;
    const int tid  = threadIdx.x;
    const int warp = tid >> 5;
    const int wm   = warp & 3;
    const int wn   = warp >> 2;

    for (int i = tid; i < 16 * NT; i += 256) sBias[i] = bi[n0 + (i % NT)];
    __syncthreads();

    wmma::fragment<wmma::accumulator, 16, 16, 16, float> acc[2][2];
    for (int i = 0; i < 2; i++)
        for (int j = 0; j < 2; j++)
            wmma::load_matrix_sync(acc[i][j], &sBias[wn * 32 + j * 16], NT,
                                   wmma::mem_row_major);

    for (int k0 = 0; k0 < D_; k0 += KT) {
        __syncthreads();
        for (int i = tid; i < MT * KT / 4; i += 256) {
            int r = i >> 3;
            int c = (i & 7) * 4;
            float4 v = *(const float4*)(X + (m0 + r) * D_ + k0 + c);
            float vs[4] = {v.x, v.y, v.z, v.w};
            #pragma unroll
            for (int q = 0; q < 4; q++) {
                __nv_bfloat16 h, l; split2(vs[q], h, l);
                sAh[r * PADA + c + q] = h;
                sAl[r * PADA + c + q] = l;
            }
        }
        for (int i = tid; i < KT * NT / 4; i += 256) {
            int r = i >> 4;
            int c = (i & 15) * 4;
            float4 v = *(const float4*)(Wi + (long long)(k0 + r) * G3H + n0 + c);
            float vs[4] = {v.x, v.y, v.z, v.w};
            #pragma unroll
            for (int q = 0; q < 4; q++) {
                __nv_bfloat16 h, l; split2(vs[q], h, l);
                sBh[r * PADB + c + q] = h;
                sBl[r * PADB + c + q] = l;
            }
        }
        __syncthreads();

        #pragma unroll
        for (int kk = 0; kk < KT; kk += 16) {
            wmma::fragment<wmma::matrix_a, 16, 16, 16, __nv_bfloat16, wmma::row_major> ah[2], al[2];
            wmma::fragment<wmma::matrix_b, 16, 16, 16, __nv_bfloat16, wmma::row_major> bh[2], bl[2];
            #pragma unroll
            for (int i = 0; i < 2; i++) {
                wmma::load_matrix_sync(ah[i], &sAh[(wm * 32 + i * 16) * PADA + kk], PADA);
                wmma::load_matrix_sync(al[i], &sAl[(wm * 32 + i * 16) * PADA + kk], PADA);
            }
            #pragma unroll
            for (int j = 0; j < 2; j++) {
                wmma::load_matrix_sync(bh[j], &sBh[kk * PADB + wn * 32 + j * 16], PADB);
                wmma::load_matrix_sync(bl[j], &sBl[kk * PADB + wn * 32 + j * 16], PADB);
            }
            #pragma unroll
            for (int i = 0; i < 2; i++)
                #pragma unroll
                for (int j = 0; j < 2; j++) {
                    wmma::mma_sync(acc[i][j], al[i], bh[j], acc[i][j]);
                    wmma::mma_sync(acc[i][j], ah[i], bl[j], acc[i][j]);
                    wmma::mma_sync(acc[i][j], ah[i], bh[j], acc[i][j]);
                }
        }
    }

    for (int i = 0; i < 2; i++)
        for (int j = 0; j < 2; j++) {
            float* p = g_Gi + (m0 + wm * 32 + i * 16) * G3H + n0 + wn * 32 + j * 16;
            wmma::store_matrix_sync(p, acc[i][j], G3H, wmma::mem_row_major);
        }
}

// ---------------------------------------------------------------------------
// Persistent scan kernel: 128 CTAs, each owns cols [j0, j0+8) of all 3 gates.
// Wh slice resident in SMEM (bf16 hi/lo). One grid barrier per step.
// ---------------------------------------------------------------------------
__global__ __launch_bounds__(256, 1) void scan_kernel(
    const float* __restrict__ h0,
    const float* __restrict__ Wh,
    const float* __restrict__ bhn,
    const void*  __restrict__ resets,
    float*       __restrict__ out)
{
    extern __shared__ __align__(16) char smem_raw[];
    __nv_bfloat16* sWh = (__nv_bfloat16*)smem_raw;            // [1024][WH_LD]
    __nv_bfloat16* sWl = sWh + H_ * WH_LD;                    // [1024][WH_LD]
    __nv_bfloat16* sAh = sWl + H_ * WH_LD;                    // [128][SA_LD]
    __nv_bfloat16* sAl = sAh + B_ * SA_LD;                    // [128][SA_LD]
    float*         sGh = (float*)(sAl + B_ * SA_LD);          // [128][GH_LD]
    unsigned char* sRst = (unsigned char*)(sGh + B_ * GH_LD); // [128]

    const int tid  = threadIdx.x;
    const int warp = tid >> 5;        // 0..7 -> 16 rows each
    const int j0   = blockIdx.x * NCOLS;

    // --- preload resident Wh slice: packed cols c: gate = c>>3, cj = c&7 ---
    for (int idx = tid; idx < H_ * NPACK; idx += 256) {
        int k = idx >> 5;
        int c = idx & 31;
        float v = 0.0f;
        if (c < 24) v = Wh[(long long)k * G3H + (c >> 3) * H_ + j0 + (c & 7)];
        __nv_bfloat16 h, l; split2(v, h, l);
        sWh[k * WH_LD + c] = h;
        sWl[k * WH_LD + c] = l;
    }
    // local bhn for this CTA's columns
    float lbhn[NCOLS];
    #pragma unroll
    for (int c = 0; c < NCOLS; c++) lbhn[c] = bhn[j0 + c];
    __syncthreads();

    for (int t = 0; t < T_; t++) {
        const float* hprev = (t == 0) ? h0 : out + (long long)(t - 1) * B_ * H_;

        if (tid < B_) sRst[tid] = get_reset(resets, t * B_ + tid) ? 1 : 0;

        wmma::fragment<wmma::accumulator, 16, 16, 16, float> acc[2];
        wmma::fill_fragment(acc[0], 0.0f);
        wmma::fill_fragment(acc[1], 0.0f);

        for (int k0 = 0; k0 < H_; k0 += SKT) {
            __syncthreads();   // protect sA reuse (and sRst on first iter)
            // stage h chunk [128 x 64], reset-masked, split hi/lo
            for (int i = tid; i < B_ * SKT / 4; i += 256) {
                int r = i >> 4;
                int c = (i & 15) * 4;
                float4 v = make_float4(0.f, 0.f, 0.f, 0.f);
                if (!sRst[r]) v = *(const float4*)(hprev + r * H_ + k0 + c);
                float vs[4] = {v.x, v.y, v.z, v.w};
                #pragma unroll
                for (int q = 0; q < 4; q++) {
                    __nv_bfloat16 h, l; split2(vs[q], h, l);
                    sAh[r * SA_LD + c + q] = h;
                    sAl[r * SA_LD + c + q] = l;
                }
            }
            __syncthreads();

            #pragma unroll
            for (int kk = 0; kk < SKT; kk += 16) {
                wmma::fragment<wmma::matrix_a, 16, 16, 16, __nv_bfloat16, wmma::row_major> ah, al;
                wmma::fragment<wmma::matrix_b, 16, 16, 16, __nv_bfloat16, wmma::row_major> bh[2], bl[2];
                wmma::load_matrix_sync(ah, &sAh[(warp * 16) * SA_LD + kk], SA_LD);
                wmma::load_matrix_sync(al, &sAl[(warp * 16) * SA_LD + kk], SA_LD);
                int kg = k0 + kk;
                #pragma unroll
                for (int j = 0; j < 2; j++) {
                    wmma::load_matrix_sync(bh[j], &sWh[kg * WH_LD + j * 16], WH_LD);
                    wmma::load_matrix_sync(bl[j], &sWl[kg * WH_LD + j * 16], WH_LD);
                }
                #pragma unroll
                for (int j = 0; j < 2; j++) {
                    wmma::mma_sync(acc[j], al, bh[j], acc[j]);
                    wmma::mma_sync(acc[j], ah, bl[j], acc[j]);
                    wmma::mma_sync(acc[j], ah, bh[j], acc[j]);
                }
            }
        }

        // --- epilogue: accs -> smem, fuse gates, write h_t ---
        __syncthreads();
        wmma::store_matrix_sync(&sGh[(warp * 16) * GH_LD + 0],  acc[0], GH_LD, wmma::mem_row_major);
        wmma::store_matrix_sync(&sGh[(warp * 16) * GH_LD + 16], acc[1], GH_LD, wmma::mem_row_major);
        __syncthreads();

        const float* gi_base = g_Gi + (long long)t * B_ * G3H;
        float* out_t = out + (long long)t * B_ * H_;
        #pragma unroll
        for (int i = 0; i < 4; i++) {
            int e  = tid + i * 256;           // 0..1023
            int b  = e >> 3;
            int cj = e & 7;
            float ghr = sGh[b * GH_LD + cj];
            float ghz = sGh[b * GH_LD + 8 + cj];
            float ghn = sGh[b * GH_LD + 16 + cj];
            const float* gi = gi_base + (long long)b * G3H;
            float ir = gi[j0 + cj];
            float iz = gi[H_ + j0 + cj];
            float in = gi[2 * H_ + j0 + cj];
            float r = 1.f / (1.f + __expf(-(ir + ghr)));
            float z = 1.f / (1.f + __expf(-(iz + ghz)));
            float n = tanhf(in + r * (ghn + lbhn[cj]));
            float hp = sRst[b] ? 0.f : hprev[b * H_ + j0 + cj];
            out_t[b * H_ + j0 + cj] = (1.f - z) * n + z * hp;
        }

        // --- grid barrier (monotonic counter; all CTAs co-resident) ---
        __syncthreads();
        if (tid == 0) {
            __threadfence();
            atomicAdd(&g_bar, 1u);
            unsigned int target = (unsigned int)gridDim.x * (unsigned int)(t + 1);
            unsigned int v;
            do {
                asm volatile("ld.acquire.gpu.u32 %0, [%1];" : "=r"(v) : "l"(&g_bar));
                if (v < target) __nanosleep(64);
            } while (v < target);
        }
        __syncthreads();
    }
}

// ---------------------------------------------------------------------------
extern "C" void kernel_launch(void* const* d_in, const int* in_sizes, int n_in,
                              void* d_out, int out_size)
{
    const float* x      = (const float*)d_in[0];
    const void*  resets = d_in[1];
    const float* h0     = (const float*)d_in[2];
    const float* Wi     = (const float*)d_in[3];
    const float* bi     = (const float*)d_in[4];
    const float* Wh     = (const float*)d_in[5];
    const float* bhn    = (const float*)d_in[6];
    float* out = (float*)d_out;

    // dynamic smem: Wh hi/lo + A stage hi/lo + gh tile + resets
    size_t smem = (size_t)(H_ * WH_LD * 2 + B_ * SA_LD * 2) * sizeof(__nv_bfloat16)
                + (size_t)B_ * GH_LD * sizeof(float) + 256;
    static int configured = 0;
    if (!configured) {
        cudaFuncSetAttribute(scan_kernel, cudaFuncAttributeMaxDynamicSharedMemorySize,
                             (int)smem);
        configured = 1;
    }

    init_kernel<<<1, 1>>>((const unsigned char*)resets);
    gi_gemm_kernel<<<dim3(G3H / NT, (T_ * B_) / MT), 256>>>(x, Wi, bi);
    scan_kernel<<<NCTA, 256, smem>>>(h0, Wh, bhn, resets, out);
}

// round 4
// speedup vs baseline: 1.6991x; 1.6991x over previous
#include <cuda_runtime.h>
#include <cuda_bf16.h>
#include <mma.h>

using namespace nvcuda;

#define T_   512
#define B_   128
#define D_   512
#define H_   1024
#define G3H  3072

// ---- gi_gemm tiling (round-2 proven, verbatim) ----
#define MT   128
#define NT   64
#define KT   32
#define PADA 40
#define PADB 72

// ---- persistent scan tiling ----
#define NCTA    128
#define NCOLS   8       // hidden cols per CTA (x3 gates = 24 packed + 8 pad)
#define NPACK   32
#define WH_LD   40      // proven geometry (round 2)
#define SKT     32      // K chunk (double-buffered)
#define SA_LD   40      // proven (same as PADA)
#define GH_LD   36

__device__ __align__(256) float         g_Gi[(long long)T_ * B_ * G3H];
__device__ __align__(256) __nv_bfloat16 g_hh[2][B_ * H_];   // masked h hi, ping-pong
__device__ __align__(256) __nv_bfloat16 g_hl[2][B_ * H_];   // masked h lo
__device__ int          g_reset_mode;
__device__ unsigned int g_bar;

// ---------------------------------------------------------------------------
__global__ void init_kernel(const unsigned char* __restrict__ resets) {
    const unsigned int* w = (const unsigned int*)resets;
    bool i32 = true, f32 = true;
    for (int i = 0; i < 16; i++) {
        unsigned int v = w[i];
        if (v != 0u && v != 1u) i32 = false;
        if (v != 0u && v != 0x3F800000u) f32 = false;
    }
    g_reset_mode = i32 ? 1 : (f32 ? 2 : 0);
    g_bar = 0u;
}

__device__ __forceinline__ bool get_reset(const void* r, int idx) {
    int m = g_reset_mode;
    if (m == 1) return ((const int*)r)[idx] != 0;
    if (m == 2) return ((const float*)r)[idx] != 0.0f;
    return ((const unsigned char*)r)[idx] != 0;
}

__device__ __forceinline__ void split2(float v, __nv_bfloat16& hi, __nv_bfloat16& lo) {
    hi = __float2bfloat16(v);
    lo = __float2bfloat16(v - __bfloat162float(hi));
}

__device__ __forceinline__ void cp16(void* smem, const void* gmem) {
    unsigned s = (unsigned)__cvta_generic_to_shared(smem);
    asm volatile("cp.async.cg.shared.global [%0], [%1], 16;" :: "r"(s), "l"(gmem));
}

// initialize masked-h scratch buffer 0 from h0 and resets[0]
__global__ void prep_h_kernel(const float* __restrict__ h0,
                              const void* __restrict__ resets)
{
    int i = blockIdx.x * 256 + threadIdx.x;   // 0 .. B*H-1
    int b = i >> 10;
    float v = get_reset(resets, b) ? 0.0f : h0[i];
    __nv_bfloat16 h, l; split2(v, h, l);
    g_hh[0][i] = h;
    g_hl[0][i] = l;
}

// ---------------------------------------------------------------------------
// Phase B: Gi = X @ Wi + bi  (round-2 proven, verbatim)
// ---------------------------------------------------------------------------
__global__ __launch_bounds__(256) void gi_gemm_kernel(
    const float* __restrict__ X,
    const float* __restrict__ Wi,
    const float* __restrict__ bi)
{
    __shared__ __align__(16) __nv_bfloat16 sAh[MT * PADA], sAl[MT * PADA];
    __shared__ __align__(16) __nv_bfloat16 sBh[KT * PADB], sBl[KT * PADB];
    __shared__ __align__(16) float sBias[16 * NT];

    const int n0  = blockIdx.x * NT;
    const long long m0 = (long long)blockIdx.y * MT;
    const int tid  = threadIdx.x;
    const int warp = tid >> 5;
    const int wm   = warp & 3;
    const int wn   = warp >> 2;

    for (int i = tid; i < 16 * NT; i += 256) sBias[i] = bi[n0 + (i % NT)];
    __syncthreads();

    wmma::fragment<wmma::accumulator, 16, 16, 16, float> acc[2][2];
    for (int i = 0; i < 2; i++)
        for (int j = 0; j < 2; j++)
            wmma::load_matrix_sync(acc[i][j], &sBias[wn * 32 + j * 16], NT,
                                   wmma::mem_row_major);

    for (int k0 = 0; k0 < D_; k0 += KT) {
        __syncthreads();
        for (int i = tid; i < MT * KT / 4; i += 256) {
            int r = i >> 3;
            int c = (i & 7) * 4;
            float4 v = *(const float4*)(X + (m0 + r) * D_ + k0 + c);
            float vs[4] = {v.x, v.y, v.z, v.w};
            #pragma unroll
            for (int q = 0; q < 4; q++) {
                __nv_bfloat16 h, l; split2(vs[q], h, l);
                sAh[r * PADA + c + q] = h;
                sAl[r * PADA + c + q] = l;
            }
        }
        for (int i = tid; i < KT * NT / 4; i += 256) {
            int r = i >> 4;
            int c = (i & 15) * 4;
            float4 v = *(const float4*)(Wi + (long long)(k0 + r) * G3H + n0 + c);
            float vs[4] = {v.x, v.y, v.z, v.w};
            #pragma unroll
            for (int q = 0; q < 4; q++) {
                __nv_bfloat16 h, l; split2(vs[q], h, l);
                sBh[r * PADB + c + q] = h;
                sBl[r * PADB + c + q] = l;
            }
        }
        __syncthreads();

        #pragma unroll
        for (int kk = 0; kk < KT; kk += 16) {
            wmma::fragment<wmma::matrix_a, 16, 16, 16, __nv_bfloat16, wmma::row_major> ah[2], al[2];
            wmma::fragment<wmma::matrix_b, 16, 16, 16, __nv_bfloat16, wmma::row_major> bh[2], bl[2];
            #pragma unroll
            for (int i = 0; i < 2; i++) {
                wmma::load_matrix_sync(ah[i], &sAh[(wm * 32 + i * 16) * PADA + kk], PADA);
                wmma::load_matrix_sync(al[i], &sAl[(wm * 32 + i * 16) * PADA + kk], PADA);
            }
            #pragma unroll
            for (int j = 0; j < 2; j++) {
                wmma::load_matrix_sync(bh[j], &sBh[kk * PADB + wn * 32 + j * 16], PADB);
                wmma::load_matrix_sync(bl[j], &sBl[kk * PADB + wn * 32 + j * 16], PADB);
            }
            #pragma unroll
            for (int i = 0; i < 2; i++)
                #pragma unroll
                for (int j = 0; j < 2; j++) {
                    wmma::mma_sync(acc[i][j], al[i], bh[j], acc[i][j]);
                    wmma::mma_sync(acc[i][j], ah[i], bl[j], acc[i][j]);
                    wmma::mma_sync(acc[i][j], ah[i], bh[j], acc[i][j]);
                }
        }
    }

    for (int i = 0; i < 2; i++)
        for (int j = 0; j < 2; j++) {
            float* p = g_Gi + (m0 + wm * 32 + i * 16) * G3H + n0 + wn * 32 + j * 16;
            wmma::store_matrix_sync(p, acc[i][j], G3H, wmma::mem_row_major);
        }
}

// ---------------------------------------------------------------------------
// Persistent scan: 128 CTAs x 512 threads (16 warps: 8M x 2N).
// Wh resident (round-2 geometry). h staged from pre-split masked bf16
// ping-pong scratch via double-buffered cp.async.cg.
// ---------------------------------------------------------------------------
__global__ __launch_bounds__(512, 1) void scan_kernel(
    const float* __restrict__ Wh,
    const float* __restrict__ bhn,
    const void*  __restrict__ resets,
    float*       __restrict__ out)
{
    extern __shared__ __align__(16) char sm[];
    __nv_bfloat16* sWh = (__nv_bfloat16*)sm;             // [1024][40]
    __nv_bfloat16* sWl = sWh + H_ * WH_LD;               // [1024][40]
    __nv_bfloat16* sStage = sWl + H_ * WH_LD;            // 2 bufs x (hi+lo) x [128][40]
    float* sGh = (float*)sStage;                         // alias (epilogue only)
    __shared__ unsigned char sRstN[B_];

    const int tid  = threadIdx.x;
    const int warp = tid >> 5;       // 0..15
    const int wm   = warp & 7;       // 8 M tiles of 16 rows
    const int wn   = warp >> 3;      // 2 N tiles: packed cols [0,16) / [16,32)
    const int j0   = blockIdx.x * NCOLS;

    // preload packed Wh slice (round-2 layout): col c<24 -> gate c>>3, col j0+(c&7)
    for (int idx = tid; idx < H_ * NPACK; idx += 512) {
        int k = idx >> 5;
        int c = idx & 31;
        float v = 0.0f;
        if (c < 24) v = Wh[(long long)k * G3H + (c >> 3) * H_ + j0 + (c & 7)];
        __nv_bfloat16 h, l; split2(v, h, l);
        sWh[k * WH_LD + c] = h;
        sWl[k * WH_LD + c] = l;
    }
    float lbhn[NCOLS];
    #pragma unroll
    for (int c = 0; c < NCOLS; c++) lbhn[c] = bhn[j0 + c];
    __syncthreads();

    const int NCHUNK = H_ / SKT;   // 32

    for (int t = 0; t < T_; t++) {
        const __nv_bfloat16* hsh = g_hh[t & 1];
        const __nv_bfloat16* hsl = g_hl[t & 1];

        if (tid < B_)
            sRstN[tid] = (t + 1 < T_) ? (get_reset(resets, (t + 1) * B_ + tid) ? 1 : 0) : 0;

        // stage chunk kc into buffer buf: one 16B cp per plane per thread
        auto stage = [&](int kc, int buf) {
            __nv_bfloat16* sh = sStage + buf * 2 * B_ * SA_LD;
            __nv_bfloat16* sl = sh + B_ * SA_LD;
            const int k0 = kc * SKT;
            int r = tid >> 2;            // 0..127
            int c = (tid & 3) * 8;       // 0,8,16,24
            cp16(&sh[r * SA_LD + c], &hsh[r * H_ + k0 + c]);
            cp16(&sl[r * SA_LD + c], &hsl[r * H_ + k0 + c]);
        };

        wmma::fragment<wmma::accumulator, 16, 16, 16, float> acc;
        wmma::fill_fragment(acc, 0.0f);

        stage(0, 0);
        asm volatile("cp.async.commit_group;");

        for (int kc = 0; kc < NCHUNK; kc++) {
            const int buf = kc & 1;
            if (kc + 1 < NCHUNK) {
                stage(kc + 1, buf ^ 1);
                asm volatile("cp.async.commit_group;");
                asm volatile("cp.async.wait_group 1;");
            } else {
                asm volatile("cp.async.wait_group 0;");
            }
            __syncthreads();

            const __nv_bfloat16* sh = sStage + buf * 2 * B_ * SA_LD;
            const __nv_bfloat16* sl = sh + B_ * SA_LD;
            #pragma unroll
            for (int kk = 0; kk < SKT; kk += 16) {
                wmma::fragment<wmma::matrix_a, 16, 16, 16, __nv_bfloat16, wmma::row_major> ah, al;
                wmma::fragment<wmma::matrix_b, 16, 16, 16, __nv_bfloat16, wmma::row_major> bh, bl;
                wmma::load_matrix_sync(ah, &sh[(wm * 16) * SA_LD + kk], SA_LD);
                wmma::load_matrix_sync(al, &sl[(wm * 16) * SA_LD + kk], SA_LD);
                int kg = kc * SKT + kk;
                wmma::load_matrix_sync(bh, &sWh[kg * WH_LD + wn * 16], WH_LD);
                wmma::load_matrix_sync(bl, &sWl[kg * WH_LD + wn * 16], WH_LD);
                wmma::mma_sync(acc, al, bh, acc);
                wmma::mma_sync(acc, ah, bl, acc);
                wmma::mma_sync(acc, ah, bh, acc);
            }
            __syncthreads();
        }

        // epilogue (round-2 mapping): acc(wn) covers packed cols [wn*16, wn*16+16)
        wmma::store_matrix_sync(&sGh[(wm * 16) * GH_LD + wn * 16], acc, GH_LD,
                                wmma::mem_row_major);
        __syncthreads();

        const float* gi_base = g_Gi + (long long)t * B_ * G3H;
        float* out_t = out + (long long)t * B_ * H_;
        #pragma unroll
        for (int s = 0; s < 2; s++) {
            int e  = tid + s * 512;     // 0..1023
            int b  = e >> 3;
            int cj = e & 7;
            float ghr = sGh[b * GH_LD + cj];
            float ghz = sGh[b * GH_LD + 8 + cj];
            float ghn = sGh[b * GH_LD + 16 + cj];
            const float* gi = gi_base + (long long)b * G3H + j0 + cj;
            float ir = gi[0];
            float iz = gi[H_];
            float in = gi[2 * H_];
            int hidx = b * H_ + j0 + cj;
            float hp = __bfloat162float(hsh[hidx]) + __bfloat162float(hsl[hidx]);
            float r = 1.f / (1.f + __expf(-(ir + ghr)));
            float z = 1.f / (1.f + __expf(-(iz + ghz)));
            float n = tanhf(in + r * (ghn + lbhn[cj]));
            float hnew = (1.f - z) * n + z * hp;
            out_t[hidx] = hnew;
            if (t + 1 < T_) {
                float m = sRstN[b] ? 0.f : hnew;
                __nv_bfloat16 h, l; split2(m, h, l);
                g_hh[(t + 1) & 1][hidx] = h;
                g_hl[(t + 1) & 1][hidx] = l;
            }
        }

        // grid barrier (round-2 proven form; all 128 CTAs co-resident)
        __syncthreads();
        if (tid == 0) {
            __threadfence();
            atomicAdd(&g_bar, 1u);
            unsigned int target = (unsigned int)gridDim.x * (unsigned int)(t + 1);
            unsigned int v;
            do {
                asm volatile("ld.acquire.gpu.u32 %0, [%1];" : "=r"(v) : "l"(&g_bar));
                if (v < target) __nanosleep(32);
            } while (v < target);
        }
        __syncthreads();
    }
}

// ---------------------------------------------------------------------------
extern "C" void kernel_launch(void* const* d_in, const int* in_sizes, int n_in,
                              void* d_out, int out_size)
{
    const float* x      = (const float*)d_in[0];
    const void*  resets = d_in[1];
    const float* h0     = (const float*)d_in[2];
    const float* Wi     = (const float*)d_in[3];
    const float* bi     = (const float*)d_in[4];
    const float* Wh     = (const float*)d_in[5];
    const float* bhn    = (const float*)d_in[6];
    float* out = (float*)d_out;

    // scan smem: Wh hi/lo [1024][40] + 2-buf stage (hi+lo) [128][40]
    const size_t scan_smem = (size_t)(2 * H_ * WH_LD + 4 * B_ * SA_LD) * sizeof(__nv_bfloat16);
    cudaFuncSetAttribute(scan_kernel, cudaFuncAttributeMaxDynamicSharedMemorySize,
                         (int)scan_smem);

    init_kernel<<<1, 1>>>((const unsigned char*)resets);
    prep_h_kernel<<<(B_ * H_) / 256, 256>>>(h0, resets);
    gi_gemm_kernel<<<dim3(G3H / NT, (T_ * B_) / MT), 256>>>(x, Wi, bi);
    scan_kernel<<<NCTA, 512, scan_smem>>>(Wh, bhn, resets, out);
}